// round 10
// baseline (speedup 1.0000x reference)
#include <cuda_runtime.h>
#include <cuda_fp16.h>
#include <cstdint>
#include <math.h>

#define M_DIM 1024
#define U_DIM 2048
#define N_DIM 8192
#define K_DIM 4096

#define BM 128
#define BUT 32
#define BK 64                                 // k per stage (4 windows of 16)
#define STAGES 3
#define TG 264                                // group stride (words); 264 % 32 = 8
#define A_WORDS (16 * TG)                     // 4224
#define B_WORDS (16 * TG)                     // 4224
#define STG_WORDS (A_WORDS + B_WORDS)         // 8448
#define STG_BYTES (STG_WORDS * 4)             // 33792
#define SMEM_BYTES (STAGES * STG_BYTES)       // 101376 -> 2 CTAs/SM
#define EP_STRIDE 132
#define NKT (K_DIM / BK)                      // 64

// Packed fp16 operands in fragment order (uint2 = half4 {k,k+1,k+8,k+9})
__device__ __align__(1024) uint2 g_ah[(size_t)M_DIM * K_DIM / 4];   // 8 MB
__device__ __align__(1024) uint2 g_wh[(size_t)N_DIM * K_DIM / 4];   // 64 MB

#define PACKA_BLOCKS 4096
#define PACKB_BLOCKS 8192

// ---------------------------------------------------------------------------
__device__ __forceinline__ void cp16(uint32_t dst, const void* src) {
    asm volatile("cp.async.cg.shared.global [%0], [%1], 16;" :: "r"(dst), "l"(src));
}
#define CP_COMMIT() asm volatile("cp.async.commit_group;" ::: "memory")
#define CP_WAIT1()  asm volatile("cp.async.wait_group 1;" ::: "memory")

__device__ __forceinline__ void mma16(float* d, uint32_t a0, uint32_t a1,
                                      uint32_t a2, uint32_t a3,
                                      uint32_t b0, uint32_t b1) {
    asm volatile(
        "mma.sync.aligned.m16n8k16.row.col.f32.f16.f16.f32 "
        "{%0,%1,%2,%3}, {%4,%5,%6,%7}, {%8,%9}, {%0,%1,%2,%3};"
        : "+f"(d[0]), "+f"(d[1]), "+f"(d[2]), "+f"(d[3])
        : "r"(a0), "r"(a1), "r"(a2), "r"(a3), "r"(b0), "r"(b1));
}

__device__ __forceinline__ float sigmoidf_(float v) { return 1.0f / (1.0f + expf(-v)); }

__device__ __forceinline__ uint32_t pack2(float lo, float hi) {
    __half2 p = __floats2half2_rn(lo, hi);
    return *reinterpret_cast<uint32_t*>(&p);
}

// ---------------------------------------------------------------------------
// Merged pack kernel (unchanged layouts).
// ---------------------------------------------------------------------------
__global__ __launch_bounds__(256)
void pack_all(const float* __restrict__ x, const float* __restrict__ h,
              const float* __restrict__ w) {
    if (blockIdx.x < PACKA_BLOCKS) {
        __shared__ float st[64][20];
        int blk = blockIdx.x;
        int m0 = (blk & 15) * 64;
        int win = blk >> 4;
        int k = win * 16;
        const float* A = (k < U_DIM) ? (x + k) : (h + (k - U_DIM));
        int tid = threadIdx.x;
        int row = tid >> 2, q = tid & 3;
        float4 v = *reinterpret_cast<const float4*>(
            A + (size_t)(m0 + row) * U_DIM + q * 4);
        *reinterpret_cast<float4*>(&st[row][q * 4]) = v;
        __syncthreads();
        int t = tid >> 6, ml = tid & 63;
        uint2 o;
        o.x = pack2(st[ml][2 * t], st[ml][2 * t + 1]);
        o.y = pack2(st[ml][2 * t + 8], st[ml][2 * t + 9]);
        g_ah[(size_t)(win * 4 + t) * M_DIM + m0 + ml] = o;
    } else {
        int idx = (blockIdx.x - PACKA_BLOCKS) * 256 + threadIdx.x;
        int G = idx >> 11, n = (idx & 2047) << 2;
        int win = G >> 2, t = G & 3;
        int k = win * 16 + 2 * t;
        const float* r0 = w + (size_t)k * N_DIM + n;
        float4 v0 = *reinterpret_cast<const float4*>(r0);
        float4 v1 = *reinterpret_cast<const float4*>(r0 + N_DIM);
        float4 v8 = *reinterpret_cast<const float4*>(r0 + 8 * (size_t)N_DIM);
        float4 v9 = *reinterpret_cast<const float4*>(r0 + 9 * (size_t)N_DIM);
        uint2* dst = &g_wh[(size_t)G * N_DIM + n];
        dst[0] = make_uint2(pack2(v0.x, v1.x), pack2(v8.x, v9.x));
        dst[1] = make_uint2(pack2(v0.y, v1.y), pack2(v8.y, v9.y));
        dst[2] = make_uint2(pack2(v0.z, v1.z), pack2(v8.z, v9.z));
        dst[3] = make_uint2(pack2(v0.w, v1.w), pack2(v8.w, v9.w));
    }
}

// ---------------------------------------------------------------------------
// Fused kernel: 512 threads, fp16 mma.sync GEMM (128m x {i,f,g,o}x32u) + gating
// ---------------------------------------------------------------------------
__global__ __launch_bounds__(512, 2)
void lstm_fused(const float* __restrict__ c, float* __restrict__ out) {
    extern __shared__ float smem[];
    const int tid = threadIdx.x;
    const int wid = tid >> 5, lane = tid & 31;
    const int g = lane >> 2, t = lane & 3;
    const int wm = wid >> 2, wn = wid & 3;        // 4 x 4 warp grid, tile 32x32
    const int bm = blockIdx.x * BM;
    const int bu = blockIdx.y * BUT;
    const uint32_t smem_b = (uint32_t)__cvta_generic_to_shared(smem);

    // ---- precomputed per-thread stage-load addressing (2 A + 2 B chunks) ---
    const int id0 = tid, id1 = tid + 512;
    const int gl0 = id0 >> 6, c0 = id0 & 63;
    const int gl1 = id1 >> 6, c1 = id1 & 63;
    const uint2* srcA0 = &g_ah[(size_t)gl0 * M_DIM + bm + c0 * 2];
    const uint2* srcA1 = &g_ah[(size_t)gl1 * M_DIM + bm + c1 * 2];
    const int nl0 = c0 * 2, nl1 = c1 * 2;
    const uint2* srcB0 = &g_wh[(size_t)gl0 * N_DIM + (nl0 >> 5) * U_DIM + bu + (nl0 & 31)];
    const uint2* srcB1 = &g_wh[(size_t)gl1 * N_DIM + (nl1 >> 5) * U_DIM + bu + (nl1 & 31)];
    const uint32_t offA0 = (gl0 * TG + c0 * 4) * 4;
    const uint32_t offA1 = (gl1 * TG + c1 * 4) * 4;
    const uint32_t offB0 = (A_WORDS + gl0 * TG + c0 * 4) * 4;
    const uint32_t offB1 = (A_WORDS + gl1 * TG + c1 * 4) * 4;

    float acc[2][4][4];
    #pragma unroll
    for (int mi = 0; mi < 2; ++mi)
        #pragma unroll
        for (int ni = 0; ni < 4; ++ni)
            #pragma unroll
            for (int q = 0; q < 4; ++q) acc[mi][ni][q] = 0.0f;

    // prologue: stages 0, 1
    #pragma unroll
    for (int s = 0; s < 2; ++s) {
        uint32_t sb = smem_b + s * STG_BYTES;
        cp16(sb + offA0, srcA0);  cp16(sb + offA1, srcA1);
        cp16(sb + offB0, srcB0);  cp16(sb + offB1, srcB1);
        CP_COMMIT();
        srcA0 += 16 * M_DIM;  srcA1 += 16 * M_DIM;
        srcB0 += 16 * N_DIM;  srcB1 += 16 * N_DIM;
    }

    int s_cur = 0, s_pre = 2;
    for (int kt = 0; kt < NKT; ++kt) {
        CP_WAIT1();
        __syncthreads();
        if (kt + 2 < NKT) {
            uint32_t sb = smem_b + s_pre * STG_BYTES;
            cp16(sb + offA0, srcA0);  cp16(sb + offA1, srcA1);
            cp16(sb + offB0, srcB0);  cp16(sb + offB1, srcB1);
            srcA0 += 16 * M_DIM;  srcA1 += 16 * M_DIM;
            srcB0 += 16 * N_DIM;  srcB1 += 16 * N_DIM;
        }
        CP_COMMIT();

        const float* stg = smem + s_cur * STG_WORDS;
        #pragma unroll
        for (int w = 0; w < 4; ++w) {
            const float2* pa = reinterpret_cast<const float2*>(
                stg + (w * 4 + t) * TG) + (wm * 32 + g);
            const float2* pb = reinterpret_cast<const float2*>(
                stg + A_WORDS + (w * 4 + t) * TG) + (wn * 32 + g);

            uint32_t af[2][4];
            #pragma unroll
            for (int mi = 0; mi < 2; ++mi) {
                float2 lo = pa[mi * 16];
                float2 hi = pa[mi * 16 + 8];
                af[mi][0] = __float_as_uint(lo.x);
                af[mi][1] = __float_as_uint(hi.x);
                af[mi][2] = __float_as_uint(lo.y);
                af[mi][3] = __float_as_uint(hi.y);
            }
            uint32_t bf[4][2];
            #pragma unroll
            for (int ni = 0; ni < 4; ++ni) {
                float2 bp = pb[ni * 8];
                bf[ni][0] = __float_as_uint(bp.x);
                bf[ni][1] = __float_as_uint(bp.y);
            }
            #pragma unroll
            for (int mi = 0; mi < 2; ++mi)
                #pragma unroll
                for (int ni = 0; ni < 4; ++ni)
                    mma16(acc[mi][ni], af[mi][0], af[mi][1], af[mi][2], af[mi][3],
                          bf[ni][0], bf[ni][1]);
        }

        s_cur = (s_cur + 1 == STAGES) ? 0 : s_cur + 1;
        s_pre = (s_pre + 1 == STAGES) ? 0 : s_pre + 1;
    }

    // ------------- epilogue: gather gates via smem, gate, write out ---------
    __syncthreads();
    float* se = smem;
    #pragma unroll
    for (int mi = 0; mi < 2; ++mi) {
        const int r0 = wm * 32 + mi * 16 + g;
        #pragma unroll
        for (int ni = 0; ni < 4; ++ni) {
            const int cb = wn * 32 + ni * 8 + 2 * t;
            *reinterpret_cast<float2*>(&se[r0 * EP_STRIDE + cb]) =
                make_float2(acc[mi][ni][0], acc[mi][ni][1]);
            *reinterpret_cast<float2*>(&se[(r0 + 8) * EP_STRIDE + cb]) =
                make_float2(acc[mi][ni][2], acc[mi][ni][3]);
        }
    }
    __syncthreads();

    const int BUsz = M_DIM * U_DIM;
    const int c4 = tid & 7;
    #pragma unroll
    for (int rep = 0; rep < 2; ++rep) {
        const int r = (tid >> 3) + rep * 64;
        const float* row = &se[r * EP_STRIDE];
        float4 iv = *reinterpret_cast<const float4*>(row + 0 * 32 + c4 * 4);
        float4 fv = *reinterpret_cast<const float4*>(row + 1 * 32 + c4 * 4);
        float4 gv = *reinterpret_cast<const float4*>(row + 2 * 32 + c4 * 4);
        float4 ov = *reinterpret_cast<const float4*>(row + 3 * 32 + c4 * 4);
        const size_t gidx = (size_t)(bm + r) * U_DIM + bu + c4 * 4;
        float4 cv = *reinterpret_cast<const float4*>(c + gidx);

        float ia[4] = {iv.x, iv.y, iv.z, iv.w};
        float fa[4] = {fv.x, fv.y, fv.z, fv.w};
        float ga[4] = {gv.x, gv.y, gv.z, gv.w};
        float oa[4] = {ov.x, ov.y, ov.z, ov.w};
        float ca[4] = {cv.x, cv.y, cv.z, cv.w};
        float hn[4], cn[4];
        #pragma unroll
        for (int q = 0; q < 4; ++q) {
            float ig = sigmoidf_(ia[q]);
            float fg = sigmoidf_(fa[q]);
            float og = sigmoidf_(oa[q]);
            float gg = tanhf(ga[q]);
            cn[q] = fg * ca[q] + ig * gg;
            hn[q] = og * tanhf(cn[q]);
        }
        float4 h4 = make_float4(hn[0], hn[1], hn[2], hn[3]);
        float4 cc4 = make_float4(cn[0], cn[1], cn[2], cn[3]);
        *reinterpret_cast<float4*>(out + gidx)            = h4;
        *reinterpret_cast<float4*>(out + BUsz + gidx)     = h4;
        *reinterpret_cast<float4*>(out + 2 * BUsz + gidx) = cc4;
    }
}

// ---------------------------------------------------------------------------
extern "C" void kernel_launch(void* const* d_in, const int* in_sizes, int n_in,
                              void* d_out, int out_size) {
    const float* x = (const float*)d_in[0];
    const float* h = (const float*)d_in[1];
    const float* c = (const float*)d_in[2];
    const float* w = (const float*)d_in[3];
    float* out = (float*)d_out;

    static int configured = 0;
    if (!configured) {
        cudaFuncSetAttribute(lstm_fused,
                             cudaFuncAttributeMaxDynamicSharedMemorySize,
                             SMEM_BYTES);
        configured = 1;
    }

    pack_all<<<PACKA_BLOCKS + PACKB_BLOCKS, 256>>>(x, h, w);

    dim3 grid(M_DIM / BM, U_DIM / BUT);   // (8, 64); x fastest -> W L2 reuse
    lstm_fused<<<grid, 512, SMEM_BYTES>>>(c, out);
}

// round 11
// speedup vs baseline: 1.2807x; 1.2807x over previous
#include <cuda_runtime.h>
#include <cuda_fp16.h>
#include <cstdint>
#include <math.h>

#define M_DIM 1024
#define U_DIM 2048
#define N_DIM 8192
#define K_DIM 4096

#define BM 128
#define BUT 32
#define BK 64                                 // k per stage
#define STAGES 3
#define STG_BYTES 32768                       // A 16K + B 16K
#define SMEM_BYTES (STAGES * STG_BYTES)       // 98304 -> 2 CTAs/SM
#define B_OFF 16384
#define EP_STRIDE 132
#define NKT (K_DIM / BK)                      // 64

// Plain fp16 operands: A row-major [M][K]; W transposed K-major [N][K]
__device__ __align__(1024) __half g_ah[(size_t)M_DIM * K_DIM];   // 8 MB
__device__ __align__(1024) __half g_wh[(size_t)N_DIM * K_DIM];   // 64 MB

// ---------------------------------------------------------------------------
__device__ __forceinline__ void cp16(uint32_t dst, const void* src) {
    asm volatile("cp.async.cg.shared.global [%0], [%1], 16;" :: "r"(dst), "l"(src));
}
#define CP_COMMIT() asm volatile("cp.async.commit_group;" ::: "memory")
#define CP_WAIT1()  asm volatile("cp.async.wait_group 1;" ::: "memory")

__device__ __forceinline__ void ldsm4(uint32_t* r, uint32_t addr) {
    asm volatile("ldmatrix.sync.aligned.m8n8.x4.shared.b16 {%0,%1,%2,%3}, [%4];"
                 : "=r"(r[0]), "=r"(r[1]), "=r"(r[2]), "=r"(r[3]) : "r"(addr));
}

__device__ __forceinline__ void mma16(float* d, uint32_t a0, uint32_t a1,
                                      uint32_t a2, uint32_t a3,
                                      uint32_t b0, uint32_t b1) {
    asm volatile(
        "mma.sync.aligned.m16n8k16.row.col.f32.f16.f16.f32 "
        "{%0,%1,%2,%3}, {%4,%5,%6,%7}, {%8,%9}, {%0,%1,%2,%3};"
        : "+f"(d[0]), "+f"(d[1]), "+f"(d[2]), "+f"(d[3])
        : "r"(a0), "r"(a1), "r"(a2), "r"(a3), "r"(b0), "r"(b1));
}

__device__ __forceinline__ float sigmoidf_(float v) { return 1.0f / (1.0f + expf(-v)); }

__device__ __forceinline__ uint32_t pack2(float lo, float hi) {
    __half2 p = __floats2half2_rn(lo, hi);
    return *reinterpret_cast<uint32_t*>(&p);
}

// ---------------------------------------------------------------------------
// Pack A = [x|h] -> fp16 row-major [M][K]. Fully coalesced.
// ---------------------------------------------------------------------------
__global__ __launch_bounds__(256)
void pack_a(const float* __restrict__ x, const float* __restrict__ h) {
    int idx = blockIdx.x * 256 + threadIdx.x;     // M*K/8 elements of 8 halves
    int m = idx >> 9;                              // K/8 = 512
    int j = (idx & 511) << 3;
    const float* src = (j < U_DIM) ? (x + (size_t)m * U_DIM + j)
                                   : (h + (size_t)m * U_DIM + (j - U_DIM));
    float4 v0 = reinterpret_cast<const float4*>(src)[0];
    float4 v1 = reinterpret_cast<const float4*>(src)[1];
    uint4 o;
    o.x = pack2(v0.x, v0.y);  o.y = pack2(v0.z, v0.w);
    o.z = pack2(v1.x, v1.y);  o.w = pack2(v1.z, v1.w);
    *reinterpret_cast<uint4*>(&g_ah[(size_t)m * K_DIM + j]) = o;
}

// ---------------------------------------------------------------------------
// Pack W [K][N] -> fp16 K-major [N][K] via 64x64 smem tile transpose.
// ---------------------------------------------------------------------------
__global__ __launch_bounds__(256)
void pack_w(const float* __restrict__ w) {
    __shared__ float st[64][65];
    int n0 = blockIdx.x * 64;                      // N/64 = 128
    int k0 = blockIdx.y * 64;                      // K/64 = 64
    int tid = threadIdx.x;
    int nx = tid & 63, ky = tid >> 6;
    #pragma unroll
    for (int r = 0; r < 16; ++r)
        st[ky + 4 * r][nx] = w[(size_t)(k0 + ky + 4 * r) * N_DIM + n0 + nx];
    __syncthreads();
    int kx = tid & 31, ny = tid >> 5;              // kx: half2 index
    #pragma unroll
    for (int r = 0; r < 8; ++r) {
        int n = ny + 8 * r;
        uint32_t o = pack2(st[2 * kx][n], st[2 * kx + 1][n]);
        *reinterpret_cast<uint32_t*>(
            &g_wh[(size_t)(n0 + n) * K_DIM + k0 + 2 * kx]) = o;
    }
}

// ---------------------------------------------------------------------------
// Fused kernel: fp16 mma.sync + ldmatrix GEMM (128m x {i,f,g,o}x32u) + gating
// Smem tile: A [128 m][64 k], B [128 n][64 k], both swizzled (chunk ^= row&7).
// ---------------------------------------------------------------------------
__global__ __launch_bounds__(256, 2)
void lstm_fused(const float* __restrict__ c, float* __restrict__ out) {
    extern __shared__ float smem[];
    const uint32_t smem_b = (uint32_t)__cvta_generic_to_shared(smem);
    const int tid = threadIdx.x;
    const int wid = tid >> 5, lane = tid & 31;
    const int g = lane >> 2, t = lane & 3;
    const int wm = wid >> 2, wn = wid & 3;        // 2 x 4 warps, warp tile 64x32
    const int bm = blockIdx.x * BM;
    const int bu = blockIdx.y * BUT;

    // ---- cp.async precompute: 8 chunks/thread (4 A + 4 B) ----
    const int crow = tid >> 3, cch = tid & 7;     // crow 0..31, cch 0..7
    const __half* srcA = g_ah + (size_t)(bm + crow) * K_DIM + cch * 8;
    const __half* srcB = g_wh + (size_t)(bu + crow) * K_DIM + cch * 8;
    const uint32_t dA = crow * 128 + ((cch ^ (crow & 7)) << 4);
    const uint32_t dB = B_OFF + dA;

    // ---- ldmatrix per-lane row bases ----
    const int khA = lane >> 4;                    // k8-half handled by this lane (A)
    const int khB = (lane >> 3) & 1;              // (B)
    uint32_t rowA[4], swA[4];
    #pragma unroll
    for (int mi = 0; mi < 4; ++mi) {
        int m = wm * 64 + mi * 16 + ((lane >> 3) & 1) * 8 + (lane & 7);
        rowA[mi] = m * 128;  swA[mi] = m & 7;
    }
    uint32_t rowB[2], swB[2];
    #pragma unroll
    for (int p = 0; p < 2; ++p) {
        int r = wn * 32 + p * 16 + (lane >> 4) * 8 + (lane & 7);
        rowB[p] = B_OFF + r * 128;  swB[p] = r & 7;
    }

    float acc[4][4][4];
    #pragma unroll
    for (int mi = 0; mi < 4; ++mi)
        #pragma unroll
        for (int ni = 0; ni < 4; ++ni)
            #pragma unroll
            for (int q = 0; q < 4; ++q) acc[mi][ni][q] = 0.0f;

    // prologue: stages 0, 1
    #pragma unroll
    for (int s = 0; s < 2; ++s) {
        uint32_t sb = smem_b + s * STG_BYTES;
        #pragma unroll
        for (int i = 0; i < 4; ++i)
            cp16(sb + dA + i * 4096, srcA + (size_t)i * 32 * K_DIM);
        #pragma unroll
        for (int i = 0; i < 4; ++i)
            cp16(sb + dB + i * 4096, srcB + (size_t)i * U_DIM * K_DIM);
        CP_COMMIT();
        srcA += BK;  srcB += BK;
    }

    int s_cur = 0, s_pre = 2;
    for (int kt = 0; kt < NKT; ++kt) {
        CP_WAIT1();
        __syncthreads();
        if (kt + 2 < NKT) {
            uint32_t sb = smem_b + s_pre * STG_BYTES;
            #pragma unroll
            for (int i = 0; i < 4; ++i)
                cp16(sb + dA + i * 4096, srcA + (size_t)i * 32 * K_DIM);
            #pragma unroll
            for (int i = 0; i < 4; ++i)
                cp16(sb + dB + i * 4096, srcB + (size_t)i * U_DIM * K_DIM);
            srcA += BK;  srcB += BK;
        }
        CP_COMMIT();

        const uint32_t sb = smem_b + s_cur * STG_BYTES;
        #pragma unroll
        for (int w = 0; w < 4; ++w) {
            const int kcA = 2 * w + khA;
            const int kcB = 2 * w + khB;
            uint32_t af[4][4];
            #pragma unroll
            for (int mi = 0; mi < 4; ++mi)
                ldsm4(af[mi], sb + rowA[mi] + ((kcA ^ swA[mi]) << 4));
            uint32_t bf[2][4];
            #pragma unroll
            for (int p = 0; p < 2; ++p)
                ldsm4(bf[p], sb + rowB[p] + ((kcB ^ swB[p]) << 4));
            #pragma unroll
            for (int mi = 0; mi < 4; ++mi)
                #pragma unroll
                for (int p = 0; p < 2; ++p)
                    #pragma unroll
                    for (int s2 = 0; s2 < 2; ++s2)
                        mma16(acc[mi][p * 2 + s2],
                              af[mi][0], af[mi][1], af[mi][2], af[mi][3],
                              bf[p][s2 * 2], bf[p][s2 * 2 + 1]);
        }

        s_cur = (s_cur + 1 == STAGES) ? 0 : s_cur + 1;
        s_pre = (s_pre + 1 == STAGES) ? 0 : s_pre + 1;
    }

    // ------------- epilogue: gather gates via smem, gate, write out ---------
    __syncthreads();
    float* se = smem;
    #pragma unroll
    for (int mi = 0; mi < 4; ++mi) {
        const int r0 = wm * 64 + mi * 16 + g;
        #pragma unroll
        for (int ni = 0; ni < 4; ++ni) {
            const int cb = wn * 32 + ni * 8 + 2 * t;
            *reinterpret_cast<float2*>(&se[r0 * EP_STRIDE + cb]) =
                make_float2(acc[mi][ni][0], acc[mi][ni][1]);
            *reinterpret_cast<float2*>(&se[(r0 + 8) * EP_STRIDE + cb]) =
                make_float2(acc[mi][ni][2], acc[mi][ni][3]);
        }
    }
    __syncthreads();

    const int BUsz = M_DIM * U_DIM;
    const int c4 = tid & 7;
    #pragma unroll
    for (int rep = 0; rep < 4; ++rep) {
        const int r = (tid >> 3) + rep * 32;
        const float* row = &se[r * EP_STRIDE];
        float4 iv = *reinterpret_cast<const float4*>(row + 0 * 32 + c4 * 4);
        float4 fv = *reinterpret_cast<const float4*>(row + 1 * 32 + c4 * 4);
        float4 gv = *reinterpret_cast<const float4*>(row + 2 * 32 + c4 * 4);
        float4 ov = *reinterpret_cast<const float4*>(row + 3 * 32 + c4 * 4);
        const size_t gidx = (size_t)(bm + r) * U_DIM + bu + c4 * 4;
        float4 cv = *reinterpret_cast<const float4*>(c + gidx);

        float ia[4] = {iv.x, iv.y, iv.z, iv.w};
        float fa[4] = {fv.x, fv.y, fv.z, fv.w};
        float ga[4] = {gv.x, gv.y, gv.z, gv.w};
        float oa[4] = {ov.x, ov.y, ov.z, ov.w};
        float ca[4] = {cv.x, cv.y, cv.z, cv.w};
        float hn[4], cn[4];
        #pragma unroll
        for (int q = 0; q < 4; ++q) {
            float ig = sigmoidf_(ia[q]);
            float fg = sigmoidf_(fa[q]);
            float og = sigmoidf_(oa[q]);
            float gg = tanhf(ga[q]);
            cn[q] = fg * ca[q] + ig * gg;
            hn[q] = og * tanhf(cn[q]);
        }
        float4 h4 = make_float4(hn[0], hn[1], hn[2], hn[3]);
        float4 cc4 = make_float4(cn[0], cn[1], cn[2], cn[3]);
        *reinterpret_cast<float4*>(out + gidx)            = h4;
        *reinterpret_cast<float4*>(out + BUsz + gidx)     = h4;
        *reinterpret_cast<float4*>(out + 2 * BUsz + gidx) = cc4;
    }
}

// ---------------------------------------------------------------------------
extern "C" void kernel_launch(void* const* d_in, const int* in_sizes, int n_in,
                              void* d_out, int out_size) {
    const float* x = (const float*)d_in[0];
    const float* h = (const float*)d_in[1];
    const float* c = (const float*)d_in[2];
    const float* w = (const float*)d_in[3];
    float* out = (float*)d_out;

    static int configured = 0;
    if (!configured) {
        cudaFuncSetAttribute(lstm_fused,
                             cudaFuncAttributeMaxDynamicSharedMemorySize,
                             SMEM_BYTES);
        configured = 1;
    }

    pack_a<<<(M_DIM * K_DIM / 8) / 256, 256>>>(x, h);
    pack_w<<<dim3(N_DIM / 64, K_DIM / 64), 256>>>(w);

    dim3 grid(M_DIM / BM, U_DIM / BUT);   // (8, 64); x fastest -> W L2 reuse
    lstm_fused<<<grid, 256, SMEM_BYTES>>>(c, out);
}